// round 4
// baseline (speedup 1.0000x reference)
#include <cuda_runtime.h>
#include <math_constants.h>
#include <cstdint>

#define BB 8192
#define CC 2048
#define NBINS 4096
#define GAMA 0.3f

// ---------------- scratch (static __device__, no allocs) ----------------
// per-row label-independent state: .x = m1 (max over cols[1,C)), .y = m2 (2nd max),
// .z = argmax col as int bits, .w unused
__device__ float4 g_res[BB];

__device__ __forceinline__ float sigmoidf_(float v) { return 1.0f / (1.0f + __expf(-v)); }
// Monotonic bin for v in (0,1): float bits order-preserving for positive floats.
__device__ __forceinline__ int binOf(float v) { return (int)(__float_as_uint(v) >> 19); }

// ---------------- K1: label-blind per-row top-2 max + argmax over cols [1,C) ----------------
__global__ __launch_bounds__(128) void k_row(const float* __restrict__ x) {
    const int row = blockIdx.x;
    const int tid = threadIdx.x;

    const float4* xr = (const float4*)(x + (size_t)row * CC);
    float m1 = -CUDART_INF_F, m2 = -CUDART_INF_F;
    int   a  = -1;
#pragma unroll 4
    for (int c4 = tid; c4 < CC / 4; c4 += 128) {
        float4 v = __ldg(xr + c4);
        int c = c4 * 4;
        if (c == 0) v.x = -CUDART_INF_F;          // exclude col 0
        { bool gt = v.x > m1; m2 = gt ? m1 : fmaxf(m2, v.x); a = gt ? c + 0 : a; m1 = gt ? v.x : m1; }
        { bool gt = v.y > m1; m2 = gt ? m1 : fmaxf(m2, v.y); a = gt ? c + 1 : a; m1 = gt ? v.y : m1; }
        { bool gt = v.z > m1; m2 = gt ? m1 : fmaxf(m2, v.z); a = gt ? c + 2 : a; m1 = gt ? v.z : m1; }
        { bool gt = v.w > m1; m2 = gt ? m1 : fmaxf(m2, v.w); a = gt ? c + 3 : a; m1 = gt ? v.w : m1; }
    }
    // warp butterfly merge of (m1, m2, a)
#pragma unroll
    for (int o = 16; o; o >>= 1) {
        float om1 = __shfl_xor_sync(0xffffffffu, m1, o);
        float om2 = __shfl_xor_sync(0xffffffffu, m2, o);
        int   oa  = __shfl_xor_sync(0xffffffffu, a,  o);
        if (om1 > m1) { m2 = fmaxf(m1, om2); m1 = om1; a = oa; }
        else          { m2 = fmaxf(m2, om1); }
    }
    __shared__ float sm1[4], sm2[4];
    __shared__ int   sa[4];
    if ((tid & 31) == 0) { int w = tid >> 5; sm1[w] = m1; sm2[w] = m2; sa[w] = a; }
    __syncthreads();
    if (tid == 0) {
        m1 = sm1[0]; m2 = sm2[0]; a = sa[0];
#pragma unroll
        for (int w = 1; w < 4; w++) {
            if (sm1[w] > m1) { m2 = fmaxf(m1, sm2[w]); m1 = sm1[w]; a = sa[w]; }
            else             { m2 = fmaxf(m2, sm1[w]); }
        }
        g_res[row] = make_float4(m1, m2, __int_as_float(a), 0.0f);
    }
}

// ---------------- K2: detect + select + hist + scan + scatter + suffix + queries ----------------
// smem layout (bytes from base):
//   [0      , 65544 )  double sS1[8193]   (overlay: float sraw[8192] @0,
//   [65544  , 131088)  double sS2[8193]    int shist[4096] @32768, int scursor[4096] @49152)
//   [131088 , 163856)  float  ssorted[8192]
//   [163856 , 180248)  int    sbinStart[4097] (+pad)
//   [180248 , 188440)  double p1[1024]
//   [188440 , 196632)  double p2[1024]
//   [196632 , 200728)  int    iscan[1024]
#define K2_SMEM 200728

__global__ __launch_bounds__(1024, 1) void k_main(const float* __restrict__ x,
                                                  const int* __restrict__ wy,
                                                  float* __restrict__ out) {
    extern __shared__ unsigned char sm[];
    double* sS1      = (double*)(sm);
    double* sS2      = (double*)(sm + 65544);
    float*  ssorted  = (float*) (sm + 131088);
    int*    sbinStart= (int*)   (sm + 163856);
    double* p1       = (double*)(sm + 180248);
    double* p2       = (double*)(sm + 188440);
    int*    iscan    = (int*)   (sm + 196632);
    float*  sraw     = (float*) (sm);           // overlay, dead before sS1 written
    int*    shist    = (int*)   (sm + 32768);   // overlay
    int*    scursor  = (int*)   (sm + 49152);   // overlay

    const int tid  = threadIdx.x;
    const int lane = tid & 31;

    // ---- phase 0: dtype detect, reading ONLY the first BB int32 words (safe for both) ----
    // int64 labels (<2048) -> odd words of the first BB words are high halves == 0.
    // int32 labels -> odd words are real labels, some nonzero.
    int f = 0;
#pragma unroll
    for (int k = 0; k < 4; k++) {
        int i = tid + k * 2048;                 // covers words [0, 8192)
        f |= wy[2 * (i & 4095) + 1] & ((i < 4096) ? -1 : 0);
    }
    for (int i = tid; i < NBINS; i += 1024) shist[i] = 0;
    const int notI64 = __syncthreads_or(f);

    // ---- phase 1: per-row select (neg, m); neg -> sraw smem, m -> regs ----
    float pm[8];
#pragma unroll
    for (int k = 0; k < 8; k++) {
        int i = tid + k * 1024;
        float4 r = g_res[i];
        int a = __float_as_int(r.z);
        // safe: wy[2*i] only dereferenced when labels proven int64 (buffer = 2*BB words)
        int yq = notI64 ? wy[i] : wy[2 * i];
        float n = (a == yq) ? r.y : r.x;        // exclude label col iff it is the argmax
        sraw[i] = sigmoidf_(n);
        pm[k] = (yq != 0) ? (sigmoidf_(__ldg(&x[(size_t)i * CC + yq])) - GAMA)
                          : CUDART_INF_F;
    }
    __syncthreads();

    // ---- phase 2: histogram (warp-aggregated atomics) ----
#pragma unroll
    for (int k = 0; k < 8; k++) {
        int b = binOf(sraw[tid + k * 1024]);
        unsigned mask = __match_any_sync(0xffffffffu, b);
        if (lane == (__ffs(mask) - 1)) atomicAdd(&shist[b], __popc(mask));
    }
    __syncthreads();

    // ---- phase 3: exclusive scan over 4096 bins ----
    const int tb = tid * 4;
    int tsum = shist[tb] + shist[tb + 1] + shist[tb + 2] + shist[tb + 3];
    iscan[tid] = tsum;
    __syncthreads();
    for (int off = 1; off < 1024; off <<= 1) {
        int v = (tid >= off) ? iscan[tid - off] : 0;
        __syncthreads();
        iscan[tid] += v;
        __syncthreads();
    }
    {
        int ex = iscan[tid] - tsum;
#pragma unroll
        for (int k = 0; k < 4; k++) {
            sbinStart[tb + k] = ex;
            scursor[tb + k]   = ex;
            ex += shist[tb + k];
        }
        if (tid == 1023) sbinStart[NBINS] = ex;   // = BB
    }
    __syncthreads();

    // ---- phase 4: scatter into bin-grouped order (warp-aggregated) ----
#pragma unroll
    for (int k = 0; k < 8; k++) {
        float v = sraw[tid + k * 1024];
        int b = binOf(v);
        unsigned mask = __match_any_sync(0xffffffffu, b);
        int leader = __ffs(mask) - 1;
        int pos0 = 0;
        if (lane == leader) pos0 = atomicAdd(&scursor[b], __popc(mask));
        pos0 = __shfl_sync(0xffffffffu, pos0, leader);
        ssorted[pos0 + __popc(mask & ((1u << lane) - 1u))] = v;
    }
    __syncthreads();   // sraw/shist/scursor dead from here

    // ---- phase 5: element-level suffix sums (double) over sorted ----
    const int base8 = tid * 8;
    double tl1[8], tl2[8];
    double a1 = 0.0, a2 = 0.0;
#pragma unroll
    for (int k = 7; k >= 0; --k) {
        float n = ssorted[base8 + k];
        a1 += (double)n;
        a2 += (double)n * (double)n;
        tl1[k] = a1; tl2[k] = a2;
    }
    p1[tid] = a1; p2[tid] = a2;
    __syncthreads();
    for (int off = 1; off < 1024; off <<= 1) {
        double v1 = (tid + off < 1024) ? p1[tid + off] : 0.0;
        double v2 = (tid + off < 1024) ? p2[tid + off] : 0.0;
        __syncthreads();
        p1[tid] += v1; p2[tid] += v2;
        __syncthreads();
    }
    {
        double o1 = p1[tid] - a1, o2 = p2[tid] - a2;
#pragma unroll
        for (int k = 0; k < 8; k++) {
            sS1[base8 + k] = tl1[k] + o1;
            sS2[base8 + k] = tl2[k] + o2;
        }
        if (tid == 0) { sS1[BB] = 0.0; sS2[BB] = 0.0; }
    }
    __syncthreads();

    // ---- phase 6: queries + reduction ----
    double acc = 0.0;
    int vc = 0;
#pragma unroll
    for (int k = 0; k < 8; k++) {
        float m = pm[k];
        if (!(m < 1.0f)) continue;       // invalid (+INF); valid m < 0.7 always
        vc++;
        long long cnt; double S1, S2;
        if (m <= 0.0f) {
            cnt = BB; S1 = sS1[0]; S2 = sS2[0];
        } else {
            int b = binOf(m); if (b > NBINS - 1) b = NBINS - 1;
            int st = sbinStart[b], en = sbinStart[b + 1];
            cnt = BB - en; S1 = sS1[en]; S2 = sS2[en];
            for (int t = st; t < en; t++) {          // exact boundary-bin scan
                float n = ssorted[t];
                if (n > m) { cnt++; S1 += (double)n; S2 += (double)n * (double)n; }
            }
        }
        double md = (double)m;
        acc += (double)cnt * md * md - 2.0 * md * S1 + S2;
    }
    __syncthreads();
    p1[tid] = acc; iscan[tid] = vc;
    __syncthreads();
    for (int s = 512; s; s >>= 1) {
        if (tid < s) { p1[tid] += p1[tid + s]; iscan[tid] += iscan[tid + s]; }
        __syncthreads();
    }
    if (tid == 0) {
        double p = (double)iscan[0];
        out[0] = (float)(p1[0] / (p + 1.0) / ((double)BB + 1.0));
    }
}

// ---------------- launch ----------------
extern "C" void kernel_launch(void* const* d_in, const int* in_sizes, int n_in,
                              void* d_out, int out_size) {
    const float* x = (const float*)d_in[0];
    const int*   y = (const int*)d_in[1];

    k_row<<<BB, 128>>>(x);
    cudaFuncSetAttribute(k_main, cudaFuncAttributeMaxDynamicSharedMemorySize, K2_SMEM);
    k_main<<<1, 1024, K2_SMEM>>>(x, y, (float*)d_out);
}

// round 5
// speedup vs baseline: 1.2835x; 1.2835x over previous
#include <cuda_runtime.h>
#include <math_constants.h>
#include <cstdint>

#define BB 8192
#define CC 2048
#define NBINS 4096
#define GAMA 0.3f

// ---------------- scratch (static __device__, no allocs) ----------------
__device__ float4 g_res[BB];   // .x=m1 (max over cols[1,C)), .y=m2, .z=argmax bits
__device__ float  g_neg[BB];   // selected sigmoid(masked max)
__device__ float  g_posm[BB];  // m_i = sigmoid(x[i,y])-gamma, +INF invalid
__device__ int    g_notI64;    // 1 = labels int32, 0 = int64

__device__ __forceinline__ float sigmoidf_(float v) { return 1.0f / (1.0f + __expf(-v)); }
// Monotonic bin for v in (0,1): positive-float bits are order-preserving.
__device__ __forceinline__ int binOf(float v) { return (int)(__float_as_uint(v) >> 19); }

// ---------------- K1: label-blind top-2 max + argmax; block 0 also detects dtype ----------------
__global__ __launch_bounds__(128) void k_row(const float* __restrict__ x,
                                             const int* __restrict__ wy) {
    const int row = blockIdx.x;
    const int tid = threadIdx.x;

    if (row == 0) {
        // dtype detect: reads only words [0, BB) — in-bounds for int32 (BB words)
        // and int64 (2*BB words). int64 -> odd words are zero high-halves.
        int f = 0;
        for (int i = tid; i < BB / 2; i += 128) f |= wy[2 * i + 1];
#pragma unroll
        for (int o = 16; o; o >>= 1) f |= __shfl_xor_sync(0xffffffffu, f, o);
        __shared__ int sf[4];
        if ((tid & 31) == 0) sf[tid >> 5] = f;
        __syncthreads();
        if (tid == 0) g_notI64 = ((sf[0] | sf[1] | sf[2] | sf[3]) != 0);
        __syncthreads();
    }

    const float4* xr = (const float4*)(x + (size_t)row * CC);
    float m1 = -CUDART_INF_F, m2 = -CUDART_INF_F;
    int   a  = -1;
#pragma unroll 4
    for (int c4 = tid; c4 < CC / 4; c4 += 128) {
        float4 v = __ldg(xr + c4);
        int c = c4 * 4;
        if (c == 0) v.x = -CUDART_INF_F;          // exclude col 0
        { bool gt = v.x > m1; m2 = gt ? m1 : fmaxf(m2, v.x); a = gt ? c + 0 : a; m1 = gt ? v.x : m1; }
        { bool gt = v.y > m1; m2 = gt ? m1 : fmaxf(m2, v.y); a = gt ? c + 1 : a; m1 = gt ? v.y : m1; }
        { bool gt = v.z > m1; m2 = gt ? m1 : fmaxf(m2, v.z); a = gt ? c + 2 : a; m1 = gt ? v.z : m1; }
        { bool gt = v.w > m1; m2 = gt ? m1 : fmaxf(m2, v.w); a = gt ? c + 3 : a; m1 = gt ? v.w : m1; }
    }
#pragma unroll
    for (int o = 16; o; o >>= 1) {
        float om1 = __shfl_xor_sync(0xffffffffu, m1, o);
        float om2 = __shfl_xor_sync(0xffffffffu, m2, o);
        int   oa  = __shfl_xor_sync(0xffffffffu, a,  o);
        if (om1 > m1) { m2 = fmaxf(m1, om2); m1 = om1; a = oa; }
        else          { m2 = fmaxf(m2, om1); }
    }
    __shared__ float sm1[4], sm2[4];
    __shared__ int   sa[4];
    if ((tid & 31) == 0) { int w = tid >> 5; sm1[w] = m1; sm2[w] = m2; sa[w] = a; }
    __syncthreads();
    if (tid == 0) {
        m1 = sm1[0]; m2 = sm2[0]; a = sa[0];
#pragma unroll
        for (int w = 1; w < 4; w++) {
            if (sm1[w] > m1) { m2 = fmaxf(m1, sm2[w]); m1 = sm1[w]; a = sa[w]; }
            else             { m2 = fmaxf(m2, sm1[w]); }
        }
        g_res[row] = make_float4(m1, m2, __int_as_float(a), 0.0f);
    }
}

// ---------------- K1b: parallel label select + pos gather (after k_row, stream-ordered) ----------------
__global__ __launch_bounds__(256) void k_pos(const float* __restrict__ x,
                                             const int* __restrict__ wy) {
    const int i = blockIdx.x * 256 + threadIdx.x;   // 32*256 = 8192
    const int notI64 = g_notI64;
    // wy[2*i] only dereferenced when labels proven int64 (buffer has 2*BB words)
    int yq = notI64 ? wy[i] : wy[2 * i];
    float4 r = g_res[i];
    int a = __float_as_int(r.z);
    float n = (a == yq) ? r.y : r.x;          // exclude label col iff it's the argmax (tie-safe)
    g_neg[i] = sigmoidf_(n);
    g_posm[i] = (yq != 0) ? (sigmoidf_(__ldg(&x[(size_t)i * CC + yq])) - GAMA)
                          : CUDART_INF_F;
}

// ---------------- K2: hist + scan + scatter + suffix + queries (all smem) ----------------
// smem layout (bytes from base):
//   [0      , 65544 )  double sS1[8193]   (overlay: float sraw[8192] @0,
//   [65544  , 131088)  double sS2[8193]    int shist[4096] @32768, int scursor[4096] @49152)
//   [131088 , 163856)  float  ssorted[8192]
//   [163856 , 180248)  int    sbinStart[4097] (+pad)
//   [180248 , 188440)  double p1[1024]
//   [188440 , 196632)  double p2[1024]
//   [196632 , 200728)  int    iscan[1024]
#define K2_SMEM 200728

__global__ __launch_bounds__(1024, 1) void k_main(float* __restrict__ out) {
    extern __shared__ unsigned char sm[];
    double* sS1      = (double*)(sm);
    double* sS2      = (double*)(sm + 65544);
    float*  ssorted  = (float*) (sm + 131088);
    int*    sbinStart= (int*)   (sm + 163856);
    double* p1       = (double*)(sm + 180248);
    double* p2       = (double*)(sm + 188440);
    int*    iscan    = (int*)   (sm + 196632);
    float*  sraw     = (float*) (sm);           // overlay, dead before sS1 written
    int*    shist    = (int*)   (sm + 32768);   // overlay
    int*    scursor  = (int*)   (sm + 49152);   // overlay

    const int tid  = threadIdx.x;
    const int lane = tid & 31;

    // ---- phase 1: contiguous loads; neg -> smem, m -> regs ----
    float pm[8];
#pragma unroll
    for (int k = 0; k < 8; k++) {
        int i = tid + k * 1024;
        sraw[i] = g_neg[i];
        pm[k]   = g_posm[i];
    }
    for (int i = tid; i < NBINS; i += 1024) shist[i] = 0;
    __syncthreads();

    // ---- phase 2: histogram (warp-aggregated atomics) ----
#pragma unroll
    for (int k = 0; k < 8; k++) {
        int b = binOf(sraw[tid + k * 1024]);
        unsigned mask = __match_any_sync(0xffffffffu, b);
        if (lane == (__ffs(mask) - 1)) atomicAdd(&shist[b], __popc(mask));
    }
    __syncthreads();

    // ---- phase 3: exclusive scan over 4096 bins ----
    const int tb = tid * 4;
    int tsum = shist[tb] + shist[tb + 1] + shist[tb + 2] + shist[tb + 3];
    iscan[tid] = tsum;
    __syncthreads();
    for (int off = 1; off < 1024; off <<= 1) {
        int v = (tid >= off) ? iscan[tid - off] : 0;
        __syncthreads();
        iscan[tid] += v;
        __syncthreads();
    }
    {
        int ex = iscan[tid] - tsum;
#pragma unroll
        for (int k = 0; k < 4; k++) {
            sbinStart[tb + k] = ex;
            scursor[tb + k]   = ex;
            ex += shist[tb + k];
        }
        if (tid == 1023) sbinStart[NBINS] = ex;   // = BB
    }
    __syncthreads();

    // ---- phase 4: scatter into bin-grouped order (warp-aggregated) ----
#pragma unroll
    for (int k = 0; k < 8; k++) {
        float v = sraw[tid + k * 1024];
        int b = binOf(v);
        unsigned mask = __match_any_sync(0xffffffffu, b);
        int leader = __ffs(mask) - 1;
        int pos0 = 0;
        if (lane == leader) pos0 = atomicAdd(&scursor[b], __popc(mask));
        pos0 = __shfl_sync(0xffffffffu, pos0, leader);
        ssorted[pos0 + __popc(mask & ((1u << lane) - 1u))] = v;
    }
    __syncthreads();   // sraw/shist/scursor dead from here

    // ---- phase 5: element-level suffix sums (double) over sorted ----
    const int base8 = tid * 8;
    double tl1[8], tl2[8];
    double a1 = 0.0, a2 = 0.0;
#pragma unroll
    for (int k = 7; k >= 0; --k) {
        float n = ssorted[base8 + k];
        a1 += (double)n;
        a2 += (double)n * (double)n;
        tl1[k] = a1; tl2[k] = a2;
    }
    p1[tid] = a1; p2[tid] = a2;
    __syncthreads();
    for (int off = 1; off < 1024; off <<= 1) {
        double v1 = (tid + off < 1024) ? p1[tid + off] : 0.0;
        double v2 = (tid + off < 1024) ? p2[tid + off] : 0.0;
        __syncthreads();
        p1[tid] += v1; p2[tid] += v2;
        __syncthreads();
    }
    {
        double o1 = p1[tid] - a1, o2 = p2[tid] - a2;
#pragma unroll
        for (int k = 0; k < 8; k++) {
            sS1[base8 + k] = tl1[k] + o1;
            sS2[base8 + k] = tl2[k] + o2;
        }
        if (tid == 0) { sS1[BB] = 0.0; sS2[BB] = 0.0; }
    }
    __syncthreads();

    // ---- phase 6: queries + reduction ----
    double acc = 0.0;
    int vc = 0;
#pragma unroll
    for (int k = 0; k < 8; k++) {
        float m = pm[k];
        if (!(m < 1.0f)) continue;       // invalid (+INF)
        vc++;
        long long cnt; double S1, S2;
        if (m <= 0.0f) {
            cnt = BB; S1 = sS1[0]; S2 = sS2[0];
        } else {
            int b = binOf(m); if (b > NBINS - 1) b = NBINS - 1;
            int st = sbinStart[b], en = sbinStart[b + 1];
            cnt = BB - en; S1 = sS1[en]; S2 = sS2[en];
            for (int t = st; t < en; t++) {          // exact boundary-bin scan
                float n = ssorted[t];
                if (n > m) { cnt++; S1 += (double)n; S2 += (double)n * (double)n; }
            }
        }
        double md = (double)m;
        acc += (double)cnt * md * md - 2.0 * md * S1 + S2;
    }
    __syncthreads();
    p1[tid] = acc; iscan[tid] = vc;
    __syncthreads();
    for (int s = 512; s; s >>= 1) {
        if (tid < s) { p1[tid] += p1[tid + s]; iscan[tid] += iscan[tid + s]; }
        __syncthreads();
    }
    if (tid == 0) {
        double p = (double)iscan[0];
        out[0] = (float)(p1[0] / (p + 1.0) / ((double)BB + 1.0));
    }
}

// ---------------- launch ----------------
extern "C" void kernel_launch(void* const* d_in, const int* in_sizes, int n_in,
                              void* d_out, int out_size) {
    const float* x = (const float*)d_in[0];
    const int*   y = (const int*)d_in[1];

    k_row<<<BB, 128>>>(x, y);
    k_pos<<<32, 256>>>(x, y);
    cudaFuncSetAttribute(k_main, cudaFuncAttributeMaxDynamicSharedMemorySize, K2_SMEM);
    k_main<<<1, 1024, K2_SMEM>>>((float*)d_out);
}

// round 7
// speedup vs baseline: 1.4198x; 1.1062x over previous
#include <cuda_runtime.h>
#include <math_constants.h>
#include <cstdint>

#define BB 8192
#define CC 2048
#define NBINS 4096
#define GAMA 0.3f
#define FULLM 0xffffffffu

// ---------------- scratch (static __device__, no allocs) ----------------
__device__ float2 g_res[BB];   // .x=m1 (max over cols[1,C)), .y=m2 (2nd max)
__device__ float  g_neg[BB];   // selected sigmoid(masked max)
__device__ float  g_posm[BB];  // m_i = sigmoid(x[i,y])-gamma, +INF invalid
__device__ int    g_notI64;    // 1 = labels int32, 0 = int64

__device__ __forceinline__ float sigmoidf_(float v) { return 1.0f / (1.0f + __expf(-v)); }
// Monotonic bin for v in (0,1): positive-float bits are order-preserving.
__device__ __forceinline__ int binOf(float v) { return (int)(__float_as_uint(v) >> 19); }

// ---------------- K1: label-blind top-2 max over cols [1,C); block 0 detects dtype ----------------
__global__ __launch_bounds__(128) void k_row(const float* __restrict__ x,
                                             const int* __restrict__ wy) {
    const int row = blockIdx.x;
    const int tid = threadIdx.x;

    if (row == 0) {
        // dtype detect: reads only words [0, BB) — in-bounds for both dtypes.
        // int64 labels (<2048) -> odd words are zero high halves.
        int f = 0;
        for (int i = tid; i < BB / 2; i += 128) f |= wy[2 * i + 1];
#pragma unroll
        for (int o = 16; o; o >>= 1) f |= __shfl_xor_sync(FULLM, f, o);
        __shared__ int sf[4];
        if ((tid & 31) == 0) sf[tid >> 5] = f;
        __syncthreads();
        if (tid == 0) g_notI64 = ((sf[0] | sf[1] | sf[2] | sf[3]) != 0);
    }

    const float4* xr = (const float4*)(x + (size_t)row * CC);
    float m1 = -CUDART_INF_F, m2 = -CUDART_INF_F;

    // thread 0 handles its first vector (containing col 0) outside the hot loop
    int c4_start = tid;
    if (tid == 0) {
        float4 v = __ldg(xr);
        float t;
        t = fminf(m1, v.y); m1 = fmaxf(m1, v.y); m2 = fmaxf(m2, t);   // skip v.x (col 0)
        t = fminf(m1, v.z); m1 = fmaxf(m1, v.z); m2 = fmaxf(m2, t);
        t = fminf(m1, v.w); m1 = fmaxf(m1, v.w); m2 = fmaxf(m2, t);
        c4_start = 128;
    }
#pragma unroll 4
    for (int c4 = c4_start; c4 < CC / 4; c4 += 128) {
        float4 v = __ldg(xr + c4);
        float t;
        t = fminf(m1, v.x); m1 = fmaxf(m1, v.x); m2 = fmaxf(m2, t);
        t = fminf(m1, v.y); m1 = fmaxf(m1, v.y); m2 = fmaxf(m2, t);
        t = fminf(m1, v.z); m1 = fmaxf(m1, v.z); m2 = fmaxf(m2, t);
        t = fminf(m1, v.w); m1 = fmaxf(m1, v.w); m2 = fmaxf(m2, t);
    }
    // warp merge of (m1, m2): new m2 = max(m2a, m2b, min(m1a, m1b))
#pragma unroll
    for (int o = 16; o; o >>= 1) {
        float om1 = __shfl_xor_sync(FULLM, m1, o);
        float om2 = __shfl_xor_sync(FULLM, m2, o);
        float lo = fminf(m1, om1);
        m1 = fmaxf(m1, om1);
        m2 = fmaxf(fmaxf(m2, om2), lo);
    }
    __shared__ float sm1[4], sm2[4];
    if ((tid & 31) == 0) { int w = tid >> 5; sm1[w] = m1; sm2[w] = m2; }
    __syncthreads();
    if (tid == 0) {
        m1 = sm1[0]; m2 = sm2[0];
#pragma unroll
        for (int w = 1; w < 4; w++) {
            float lo = fminf(m1, sm1[w]);
            m1 = fmaxf(m1, sm1[w]);
            m2 = fmaxf(fmaxf(m2, sm2[w]), lo);
        }
        g_res[row] = make_float2(m1, m2);
    }
}

// ---------------- K1b: parallel label select + pos gather ----------------
__global__ __launch_bounds__(256) void k_pos(const float* __restrict__ x,
                                             const int* __restrict__ wy) {
    const int i = blockIdx.x * 256 + threadIdx.x;   // 32*256 = 8192
    const int notI64 = g_notI64;
    // wy[2*i] only dereferenced when labels proven int64 (buffer has 2*BB words)
    int yq = notI64 ? wy[i] : wy[2 * i];
    float2 r = g_res[i];
    float px = __ldg(&x[(size_t)i * CC + yq]);
    // exact: if label col holds the max, excluding it leaves m2 (ties give m2==m1)
    float n = (yq != 0 && px == r.x) ? r.y : r.x;
    g_neg[i]  = sigmoidf_(n);
    g_posm[i] = (yq != 0) ? (sigmoidf_(px) - GAMA) : CUDART_INF_F;
}

// ---------------- K2: hist + scan + scatter + suffix + queries (all smem, warp scans) ----------------
// smem layout (bytes from base):
//   [0      , 65544 )  double sS1[8193]   (overlay: float sraw[8192] @0,
//   [65544  , 131088)  double sS2[8193]    int shist[4096] @32768, int scursor[4096] @49152)
//   [131088 , 163856)  float  ssorted[8192]
//   [163856 , 180248)  int    sbinStart[4097] (+pad)
//   [180248 , 188440)  double p1[1024]
//   [188440 , 196632)  double p2[1024]
//   [196632 , 200728)  int    iscan[1024]
#define K2_SMEM 200728

__global__ __launch_bounds__(1024, 1) void k_main(float* __restrict__ out) {
    extern __shared__ unsigned char sm[];
    double* sS1      = (double*)(sm);
    double* sS2      = (double*)(sm + 65544);
    float*  ssorted  = (float*) (sm + 131088);
    int*    sbinStart= (int*)   (sm + 163856);
    double* p1       = (double*)(sm + 180248);
    double* p2       = (double*)(sm + 188440);
    int*    iscan    = (int*)   (sm + 196632);
    float*  sraw     = (float*) (sm);           // overlay, dead before sS1 written
    int*    shist    = (int*)   (sm + 32768);   // overlay
    int*    scursor  = (int*)   (sm + 49152);   // overlay

    const int tid  = threadIdx.x;
    const int lane = tid & 31;
    const int wid  = tid >> 5;

    // ---- phase 1: contiguous loads; neg -> smem, m -> regs ----
    float pm[8];
#pragma unroll
    for (int k = 0; k < 8; k++) {
        int i = tid + k * 1024;
        sraw[i] = g_neg[i];
        pm[k]   = g_posm[i];
    }
    for (int i = tid; i < NBINS; i += 1024) shist[i] = 0;
    __syncthreads();

    // ---- phase 2: histogram (warp-aggregated atomics) ----
#pragma unroll
    for (int k = 0; k < 8; k++) {
        int b = binOf(sraw[tid + k * 1024]);
        unsigned mask = __match_any_sync(FULLM, b);
        if (lane == (__ffs(mask) - 1)) atomicAdd(&shist[b], __popc(mask));
    }
    __syncthreads();

    // ---- phase 3: exclusive scan over 4096 bins (warp-shuffle scan) ----
    const int tb = tid * 4;
    int h0 = shist[tb], h1 = shist[tb + 1], h2 = shist[tb + 2], h3 = shist[tb + 3];
    int tsum = h0 + h1 + h2 + h3;
    int v = tsum;
#pragma unroll
    for (int o = 1; o < 32; o <<= 1) {
        int t = __shfl_up_sync(FULLM, v, o);
        if (lane >= o) v += t;
    }
    if (lane == 31) iscan[wid] = v;             // warp totals
    __syncthreads();
    if (wid == 0) {
        int w = iscan[lane];
        int s = w;
#pragma unroll
        for (int o = 1; o < 32; o <<= 1) {
            int t = __shfl_up_sync(FULLM, s, o);
            if (lane >= o) s += t;
        }
        iscan[32 + lane] = s - w;               // exclusive warp offsets
    }
    __syncthreads();
    {
        int ex = v + iscan[32 + wid] - tsum;    // exclusive prefix for this thread
        sbinStart[tb] = ex;     scursor[tb]     = ex; ex += h0;
        sbinStart[tb + 1] = ex; scursor[tb + 1] = ex; ex += h1;
        sbinStart[tb + 2] = ex; scursor[tb + 2] = ex; ex += h2;
        sbinStart[tb + 3] = ex; scursor[tb + 3] = ex; ex += h3;
        if (tid == 1023) sbinStart[NBINS] = ex; // = BB
    }
    __syncthreads();

    // ---- phase 4: scatter into bin-grouped order (warp-aggregated) ----
#pragma unroll
    for (int k = 0; k < 8; k++) {
        float val = sraw[tid + k * 1024];
        int b = binOf(val);
        unsigned mask = __match_any_sync(FULLM, b);
        int leader = __ffs(mask) - 1;
        int pos0 = 0;
        if (lane == leader) pos0 = atomicAdd(&scursor[b], __popc(mask));
        pos0 = __shfl_sync(FULLM, pos0, leader);
        ssorted[pos0 + __popc(mask & ((1u << lane) - 1u))] = val;
    }
    __syncthreads();   // sraw/shist/scursor dead from here

    // ---- phase 5: element-level suffix sums (double), warp-shuffle suffix scan ----
    const int base8 = tid * 8;
    double tl1[8], tl2[8];
    double a1 = 0.0, a2 = 0.0;
#pragma unroll
    for (int k = 7; k >= 0; --k) {
        float n = ssorted[base8 + k];
        a1 += (double)n;
        a2 += (double)n * (double)n;
        tl1[k] = a1; tl2[k] = a2;
    }
    double s1 = a1, s2 = a2;
#pragma unroll
    for (int o = 1; o < 32; o <<= 1) {
        double t1 = __shfl_down_sync(FULLM, s1, o);
        double t2 = __shfl_down_sync(FULLM, s2, o);
        if (lane + o < 32) { s1 += t1; s2 += t2; }
    }
    // s1/s2 now inclusive suffix within warp (lanes [lane..31])
    if (lane == 0) { p1[wid] = s1; p2[wid] = s2; }  // warp totals
    __syncthreads();
    if (wid == 0) {
        double w1 = p1[lane], w2 = p2[lane];
        double e1 = w1, e2 = w2;
#pragma unroll
        for (int o = 1; o < 32; o <<= 1) {
            double t1 = __shfl_down_sync(FULLM, e1, o);
            double t2 = __shfl_down_sync(FULLM, e2, o);
            if (lane + o < 32) { e1 += t1; e2 += t2; }
        }
        p1[32 + lane] = e1 - w1;               // exclusive suffix of higher warps
        p2[32 + lane] = e2 - w2;
    }
    __syncthreads();
    {
        double o1 = s1 + p1[32 + wid] - a1;    // sum strictly after this thread's chunk
        double o2 = s2 + p2[32 + wid] - a2;
#pragma unroll
        for (int k = 0; k < 8; k++) {
            sS1[base8 + k] = tl1[k] + o1;
            sS2[base8 + k] = tl2[k] + o2;
        }
        if (tid == 0) { sS1[BB] = 0.0; sS2[BB] = 0.0; }
    }
    __syncthreads();

    // ---- phase 6: queries + warp reduction ----
    double acc = 0.0;
    int vc = 0;
#pragma unroll
    for (int k = 0; k < 8; k++) {
        float m = pm[k];
        if (!(m < 1.0f)) continue;       // invalid (+INF)
        vc++;
        long long cnt; double S1, S2;
        if (m <= 0.0f) {
            cnt = BB; S1 = sS1[0]; S2 = sS2[0];
        } else {
            int b = binOf(m); if (b > NBINS - 1) b = NBINS - 1;
            int st = sbinStart[b], en = sbinStart[b + 1];
            cnt = BB - en; S1 = sS1[en]; S2 = sS2[en];
            for (int t = st; t < en; t++) {          // exact boundary-bin scan
                float n = ssorted[t];
                if (n > m) { cnt++; S1 += (double)n; S2 += (double)n * (double)n; }
            }
        }
        double md = (double)m;
        acc += (double)cnt * md * md - 2.0 * md * S1 + S2;
    }
#pragma unroll
    for (int o = 16; o; o >>= 1) {
        acc += __shfl_down_sync(FULLM, acc, o);
        vc  += __shfl_down_sync(FULLM, vc,  o);
    }
    if (lane == 0) { p1[wid] = acc; iscan[wid] = vc; }
    __syncthreads();
    if (tid == 0) {
        double s = 0.0; int c = 0;
#pragma unroll
        for (int w = 0; w < 32; w++) { s += p1[w]; c += iscan[w]; }
        out[0] = (float)(s / ((double)c + 1.0) / ((double)BB + 1.0));
    }
}

// ---------------- launch ----------------
extern "C" void kernel_launch(void* const* d_in, const int* in_sizes, int n_in,
                              void* d_out, int out_size) {
    const float* x = (const float*)d_in[0];
    const int*   y = (const int*)d_in[1];

    k_row<<<BB, 128>>>(x, y);
    k_pos<<<32, 256>>>(x, y);
    cudaFuncSetAttribute(k_main, cudaFuncAttributeMaxDynamicSharedMemorySize, K2_SMEM);
    k_main<<<1, 1024, K2_SMEM>>>((float*)d_out);
}

// round 8
// speedup vs baseline: 1.4557x; 1.0253x over previous
#include <cuda_runtime.h>
#include <math_constants.h>
#include <cstdint>

#define BB 8192
#define CC 2048
#define NBINS 4096
#define GAMA 0.3f
#define FULLM 0xffffffffu

// ---------------- scratch (static __device__, no allocs) ----------------
__device__ float g_rowmax[BB]; // max over cols [1,C)
__device__ float g_neg[BB];    // sigmoid(max excluding label col and col 0)
__device__ float g_posm[BB];   // m_i = sigmoid(x[i,y])-gamma, +INF invalid
__device__ int   g_notI64;     // 1 = labels int32, 0 = int64

__device__ __forceinline__ float sigmoidf_(float v) { return 1.0f / (1.0f + __expf(-v)); }
// Monotonic bin for v in (0,1): positive-float bits are order-preserving.
__device__ __forceinline__ int binOf(float v) { return (int)(__float_as_uint(v) >> 19); }

// ---------------- K1: max over cols [1,C); block 0 also detects label dtype ----------------
__global__ __launch_bounds__(128) void k_row(const float* __restrict__ x,
                                             const int* __restrict__ wy) {
    const int row = blockIdx.x;
    const int tid = threadIdx.x;

    if (row == 0) {
        // dtype detect: reads only words [0, BB) — in-bounds for both dtypes.
        // int64 labels (<2048) -> odd words are zero high halves.
        int f = 0;
        for (int i = tid; i < BB / 2; i += 128) f |= wy[2 * i + 1];
#pragma unroll
        for (int o = 16; o; o >>= 1) f |= __shfl_xor_sync(FULLM, f, o);
        __shared__ int sf[4];
        if ((tid & 31) == 0) sf[tid >> 5] = f;
        __syncthreads();
        if (tid == 0) g_notI64 = ((sf[0] | sf[1] | sf[2] | sf[3]) != 0);
    }

    const float4* xr = (const float4*)(x + (size_t)row * CC);
    float mx = -CUDART_INF_F;

    int c4 = tid;
    if (tid == 0) {                       // vector containing col 0, handled off the hot path
        float4 v = __ldg(xr);
        mx = fmaxf(fmaxf(v.y, v.z), v.w);
        c4 = 128;
    }
#pragma unroll 4
    for (; c4 < CC / 4; c4 += 128) {
        float4 v = __ldg(xr + c4);
        mx = fmaxf(mx, fmaxf(fmaxf(v.x, v.y), fmaxf(v.z, v.w)));
    }
#pragma unroll
    for (int o = 16; o; o >>= 1) mx = fmaxf(mx, __shfl_xor_sync(FULLM, mx, o));
    __shared__ float wmax[4];
    if ((tid & 31) == 0) wmax[tid >> 5] = mx;
    __syncthreads();
    if (tid == 0)
        g_rowmax[row] = fmaxf(fmaxf(wmax[0], wmax[1]), fmaxf(wmax[2], wmax[3]));
}

// ---------------- K1b: label select + pos gather; rare cooperative rescan ----------------
__global__ __launch_bounds__(256) void k_pos(const float* __restrict__ x,
                                             const int* __restrict__ wy) {
    const int i    = blockIdx.x * 256 + threadIdx.x;   // 32*256 = 8192
    const int lane = threadIdx.x & 31;
    const int notI64 = g_notI64;
    // wy[2*i] only dereferenced when labels proven int64 (buffer has 2*BB words)
    int yq = notI64 ? wy[i] : wy[2 * i];
    float m1 = g_rowmax[i];
    float px = __ldg(&x[(size_t)i * CC + yq]);

    float neg = m1;                       // correct unless label col holds the max
    bool need = (yq != 0) && (px == m1);  // exact: px is an element, m1 the exact max
    unsigned bal = __ballot_sync(FULLM, need);
    while (bal) {                         // ~4 rows expected across the whole grid
        int l  = __ffs(bal) - 1; bal &= bal - 1;
        int ri = __shfl_sync(FULLM, i,  l);
        int ry = __shfl_sync(FULLM, yq, l);
        const float4* xr = (const float4*)(x + (size_t)ri * CC);
        float mm = -CUDART_INF_F;
        for (int c4 = lane; c4 < CC / 4; c4 += 32) {
            float4 v = __ldg(xr + c4);
            int c = c4 * 4;
            if (c == 0)      v.x = -CUDART_INF_F;
            if (c + 0 == ry) v.x = -CUDART_INF_F;
            if (c + 1 == ry) v.y = -CUDART_INF_F;
            if (c + 2 == ry) v.z = -CUDART_INF_F;
            if (c + 3 == ry) v.w = -CUDART_INF_F;
            mm = fmaxf(mm, fmaxf(fmaxf(v.x, v.y), fmaxf(v.z, v.w)));
        }
#pragma unroll
        for (int o = 16; o; o >>= 1) mm = fmaxf(mm, __shfl_xor_sync(FULLM, mm, o));
        if (lane == l) neg = mm;          // exact masked max for this row
    }
    g_neg[i]  = sigmoidf_(neg);
    g_posm[i] = (yq != 0) ? (sigmoidf_(px) - GAMA) : CUDART_INF_F;
}

// ---------------- K2: hist + scan + scatter + suffix + queries (all smem, warp scans) ----------------
// smem layout (bytes from base):
//   [0      , 65544 )  double sS1[8193]   (overlay: float sraw[8192] @0,
//   [65544  , 131088)  double sS2[8193]    int shist[4096] @32768, int scursor[4096] @49152)
//   [131088 , 163856)  float  ssorted[8192]
//   [163856 , 180248)  int    sbinStart[4097] (+pad)
//   [180248 , 188440)  double p1[1024]
//   [188440 , 196632)  double p2[1024]
//   [196632 , 200728)  int    iscan[1024]
#define K2_SMEM 200728

__global__ __launch_bounds__(1024, 1) void k_main(float* __restrict__ out) {
    extern __shared__ unsigned char sm[];
    double* sS1      = (double*)(sm);
    double* sS2      = (double*)(sm + 65544);
    float*  ssorted  = (float*) (sm + 131088);
    int*    sbinStart= (int*)   (sm + 163856);
    double* p1       = (double*)(sm + 180248);
    double* p2       = (double*)(sm + 188440);
    int*    iscan    = (int*)   (sm + 196632);
    float*  sraw     = (float*) (sm);           // overlay, dead before sS1 written
    int*    shist    = (int*)   (sm + 32768);   // overlay
    int*    scursor  = (int*)   (sm + 49152);   // overlay

    const int tid  = threadIdx.x;
    const int lane = tid & 31;
    const int wid  = tid >> 5;

    // ---- phase 1: contiguous loads; neg -> smem, m -> regs ----
    float pm[8];
#pragma unroll
    for (int k = 0; k < 8; k++) {
        int i = tid + k * 1024;
        sraw[i] = g_neg[i];
        pm[k]   = g_posm[i];
    }
    for (int i = tid; i < NBINS; i += 1024) shist[i] = 0;
    __syncthreads();

    // ---- phase 2: histogram (warp-aggregated atomics) ----
#pragma unroll
    for (int k = 0; k < 8; k++) {
        int b = binOf(sraw[tid + k * 1024]);
        unsigned mask = __match_any_sync(FULLM, b);
        if (lane == (__ffs(mask) - 1)) atomicAdd(&shist[b], __popc(mask));
    }
    __syncthreads();

    // ---- phase 3: exclusive scan over 4096 bins (warp-shuffle scan) ----
    const int tb = tid * 4;
    int h0 = shist[tb], h1 = shist[tb + 1], h2 = shist[tb + 2], h3 = shist[tb + 3];
    int tsum = h0 + h1 + h2 + h3;
    int v = tsum;
#pragma unroll
    for (int o = 1; o < 32; o <<= 1) {
        int t = __shfl_up_sync(FULLM, v, o);
        if (lane >= o) v += t;
    }
    if (lane == 31) iscan[wid] = v;             // warp totals
    __syncthreads();
    if (wid == 0) {
        int w = iscan[lane];
        int s = w;
#pragma unroll
        for (int o = 1; o < 32; o <<= 1) {
            int t = __shfl_up_sync(FULLM, s, o);
            if (lane >= o) s += t;
        }
        iscan[32 + lane] = s - w;               // exclusive warp offsets
    }
    __syncthreads();
    {
        int ex = v + iscan[32 + wid] - tsum;    // exclusive prefix for this thread
        sbinStart[tb] = ex;     scursor[tb]     = ex; ex += h0;
        sbinStart[tb + 1] = ex; scursor[tb + 1] = ex; ex += h1;
        sbinStart[tb + 2] = ex; scursor[tb + 2] = ex; ex += h2;
        sbinStart[tb + 3] = ex; scursor[tb + 3] = ex; ex += h3;
        if (tid == 1023) sbinStart[NBINS] = ex; // = BB
    }
    __syncthreads();

    // ---- phase 4: scatter into bin-grouped order (warp-aggregated) ----
#pragma unroll
    for (int k = 0; k < 8; k++) {
        float val = sraw[tid + k * 1024];
        int b = binOf(val);
        unsigned mask = __match_any_sync(FULLM, b);
        int leader = __ffs(mask) - 1;
        int pos0 = 0;
        if (lane == leader) pos0 = atomicAdd(&scursor[b], __popc(mask));
        pos0 = __shfl_sync(FULLM, pos0, leader);
        ssorted[pos0 + __popc(mask & ((1u << lane) - 1u))] = val;
    }
    __syncthreads();   // sraw/shist/scursor dead from here

    // ---- phase 5: element-level suffix sums (double), warp-shuffle suffix scan ----
    const int base8 = tid * 8;
    double tl1[8], tl2[8];
    double a1 = 0.0, a2 = 0.0;
#pragma unroll
    for (int k = 7; k >= 0; --k) {
        float n = ssorted[base8 + k];
        a1 += (double)n;
        a2 += (double)n * (double)n;
        tl1[k] = a1; tl2[k] = a2;
    }
    double s1 = a1, s2 = a2;
#pragma unroll
    for (int o = 1; o < 32; o <<= 1) {
        double t1 = __shfl_down_sync(FULLM, s1, o);
        double t2 = __shfl_down_sync(FULLM, s2, o);
        if (lane + o < 32) { s1 += t1; s2 += t2; }
    }
    if (lane == 0) { p1[wid] = s1; p2[wid] = s2; }  // warp totals
    __syncthreads();
    if (wid == 0) {
        double w1 = p1[lane], w2 = p2[lane];
        double e1 = w1, e2 = w2;
#pragma unroll
        for (int o = 1; o < 32; o <<= 1) {
            double t1 = __shfl_down_sync(FULLM, e1, o);
            double t2 = __shfl_down_sync(FULLM, e2, o);
            if (lane + o < 32) { e1 += t1; e2 += t2; }
        }
        p1[32 + lane] = e1 - w1;               // exclusive suffix of higher warps
        p2[32 + lane] = e2 - w2;
    }
    __syncthreads();
    {
        double o1 = s1 + p1[32 + wid] - a1;    // sum strictly after this thread's chunk
        double o2 = s2 + p2[32 + wid] - a2;
#pragma unroll
        for (int k = 0; k < 8; k++) {
            sS1[base8 + k] = tl1[k] + o1;
            sS2[base8 + k] = tl2[k] + o2;
        }
        if (tid == 0) { sS1[BB] = 0.0; sS2[BB] = 0.0; }
    }
    __syncthreads();

    // ---- phase 6: queries + warp reduction ----
    double acc = 0.0;
    int vc = 0;
#pragma unroll
    for (int k = 0; k < 8; k++) {
        float m = pm[k];
        if (!(m < 1.0f)) continue;       // invalid (+INF)
        vc++;
        long long cnt; double S1, S2;
        if (m <= 0.0f) {
            cnt = BB; S1 = sS1[0]; S2 = sS2[0];
        } else {
            int b = binOf(m); if (b > NBINS - 1) b = NBINS - 1;
            int st = sbinStart[b], en = sbinStart[b + 1];
            cnt = BB - en; S1 = sS1[en]; S2 = sS2[en];
            for (int t = st; t < en; t++) {          // exact boundary-bin scan
                float n = ssorted[t];
                if (n > m) { cnt++; S1 += (double)n; S2 += (double)n * (double)n; }
            }
        }
        double md = (double)m;
        acc += (double)cnt * md * md - 2.0 * md * S1 + S2;
    }
#pragma unroll
    for (int o = 16; o; o >>= 1) {
        acc += __shfl_down_sync(FULLM, acc, o);
        vc  += __shfl_down_sync(FULLM, vc,  o);
    }
    if (lane == 0) { p1[wid] = acc; iscan[wid] = vc; }
    __syncthreads();
    if (tid == 0) {
        double s = 0.0; int c = 0;
#pragma unroll
        for (int w = 0; w < 32; w++) { s += p1[w]; c += iscan[w]; }
        out[0] = (float)(s / ((double)c + 1.0) / ((double)BB + 1.0));
    }
}

// ---------------- launch ----------------
extern "C" void kernel_launch(void* const* d_in, const int* in_sizes, int n_in,
                              void* d_out, int out_size) {
    const float* x = (const float*)d_in[0];
    const int*   y = (const int*)d_in[1];

    k_row<<<BB, 128>>>(x, y);
    k_pos<<<32, 256>>>(x, y);
    cudaFuncSetAttribute(k_main, cudaFuncAttributeMaxDynamicSharedMemorySize, K2_SMEM);
    k_main<<<1, 1024, K2_SMEM>>>((float*)d_out);
}

// round 9
// speedup vs baseline: 1.5862x; 1.0897x over previous
#include <cuda_runtime.h>
#include <math_constants.h>
#include <cstdint>

#define BB 8192
#define CC 2048
#define NBINS 4096
#define GAMA 0.3f
#define FULLM 0xffffffffu

// ---------------- scratch (static __device__, no allocs) ----------------
__device__ float g_rowmax[BB]; // max over cols [1,C)
__device__ float g_neg[BB];    // sigmoid(max excluding label col and col 0)
__device__ float g_posm[BB];   // m_i = sigmoid(x[i,y])-gamma, +INF invalid
__device__ int   g_notI64;     // 1 = labels int32, 0 = int64

__device__ __forceinline__ float sigmoidf_(float v) { return 1.0f / (1.0f + __expf(-v)); }
// Monotonic bin for v in (0,1): positive-float bits are order-preserving.
__device__ __forceinline__ int binOf(float v) { return (int)(__float_as_uint(v) >> 19); }

__device__ __forceinline__ float max4(float4 v) {
    return fmaxf(fmaxf(v.x, v.y), fmaxf(v.z, v.w));
}

// ---------------- K1: max over cols [1,C); block 0 also detects label dtype ----------------
// 4 unconditional front-batched LDG.128 per thread (MLP_p1 = 4).
__global__ __launch_bounds__(128) void k_row(const float* __restrict__ x,
                                             const int* __restrict__ wy) {
    const int row = blockIdx.x;
    const int tid = threadIdx.x;

    const float4* xr = (const float4*)(x + (size_t)row * CC);
    // issue all 4 loads before any dependent math
    float4 v0 = __ldg(xr + tid);
    float4 v1 = __ldg(xr + tid + 128);
    float4 v2 = __ldg(xr + tid + 256);
    float4 v3 = __ldg(xr + tid + 384);

    if (row == 0) {
        // dtype detect: reads only words [0, BB) — in-bounds for both dtypes.
        // int64 labels (<2048) -> odd words are zero high halves.
        int f = 0;
        for (int i = tid; i < BB / 2; i += 128) f |= wy[2 * i + 1];
#pragma unroll
        for (int o = 16; o; o >>= 1) f |= __shfl_xor_sync(FULLM, f, o);
        __shared__ int sf[4];
        if ((tid & 31) == 0) sf[tid >> 5] = f;
        __syncthreads();
        if (tid == 0) g_notI64 = ((sf[0] | sf[1] | sf[2] | sf[3]) != 0);
    }

    if (tid == 0) v0.x = -CUDART_INF_F;   // exclude col 0
    float mx = fmaxf(fmaxf(max4(v0), max4(v1)), fmaxf(max4(v2), max4(v3)));
#pragma unroll
    for (int o = 16; o; o >>= 1) mx = fmaxf(mx, __shfl_xor_sync(FULLM, mx, o));
    __shared__ float wmax[4];
    if ((tid & 31) == 0) wmax[tid >> 5] = mx;
    __syncthreads();
    if (tid == 0)
        g_rowmax[row] = fmaxf(fmaxf(wmax[0], wmax[1]), fmaxf(wmax[2], wmax[3]));
}

// ---------------- K1b: label select + pos gather; rare cooperative rescan ----------------
__global__ __launch_bounds__(256) void k_pos(const float* __restrict__ x,
                                             const int* __restrict__ wy) {
    const int i    = blockIdx.x * 256 + threadIdx.x;   // 32*256 = 8192
    const int lane = threadIdx.x & 31;
    const int notI64 = g_notI64;
    // wy[2*i] only dereferenced when labels proven int64 (buffer has 2*BB words)
    int yq = notI64 ? wy[i] : wy[2 * i];
    float m1 = g_rowmax[i];
    float px = __ldg(&x[(size_t)i * CC + yq]);

    float neg = m1;                       // correct unless label col holds the max
    bool need = (yq != 0) && (px == m1);  // exact: px is an element, m1 the exact max
    unsigned bal = __ballot_sync(FULLM, need);
    while (bal) {                         // ~4 rows expected across the whole grid
        int l  = __ffs(bal) - 1; bal &= bal - 1;
        int ri = __shfl_sync(FULLM, i,  l);
        int ry = __shfl_sync(FULLM, yq, l);
        const float4* xr = (const float4*)(x + (size_t)ri * CC);
        float mm = -CUDART_INF_F;
        for (int c4 = lane; c4 < CC / 4; c4 += 32) {
            float4 v = __ldg(xr + c4);
            int c = c4 * 4;
            if (c == 0)      v.x = -CUDART_INF_F;
            if (c + 0 == ry) v.x = -CUDART_INF_F;
            if (c + 1 == ry) v.y = -CUDART_INF_F;
            if (c + 2 == ry) v.z = -CUDART_INF_F;
            if (c + 3 == ry) v.w = -CUDART_INF_F;
            mm = fmaxf(mm, max4(v));
        }
#pragma unroll
        for (int o = 16; o; o >>= 1) mm = fmaxf(mm, __shfl_xor_sync(FULLM, mm, o));
        if (lane == l) neg = mm;          // exact masked max for this row
    }
    g_neg[i]  = sigmoidf_(neg);
    g_posm[i] = (yq != 0) ? (sigmoidf_(px) - GAMA) : CUDART_INF_F;
}

// ---------------- K2: hist + scan + scatter + suffix + queries (all smem, warp scans) ----------------
// smem layout (bytes from base):
//   [0      , 65544 )  double sS1[8193]   (overlay: float sraw[8192] @0,
//   [65544  , 131088)  double sS2[8193]    int shist[4096] @32768, int scursor[4096] @49152)
//   [131088 , 163856)  float  ssorted[8192]
//   [163856 , 180248)  int    sbinStart[4097] (+pad)
//   [180248 , 188440)  double p1[1024]
//   [188440 , 196632)  double p2[1024]
//   [196632 , 200728)  int    iscan[1024]
#define K2_SMEM 200728

__global__ __launch_bounds__(1024, 1) void k_main(float* __restrict__ out) {
    extern __shared__ unsigned char sm[];
    double* sS1      = (double*)(sm);
    double* sS2      = (double*)(sm + 65544);
    float*  ssorted  = (float*) (sm + 131088);
    int*    sbinStart= (int*)   (sm + 163856);
    double* p1       = (double*)(sm + 180248);
    double* p2       = (double*)(sm + 188440);
    int*    iscan    = (int*)   (sm + 196632);
    float*  sraw     = (float*) (sm);           // overlay, dead before sS1 written
    int*    shist    = (int*)   (sm + 32768);   // overlay
    int*    scursor  = (int*)   (sm + 49152);   // overlay

    const int tid  = threadIdx.x;
    const int lane = tid & 31;
    const int wid  = tid >> 5;

    // ---- phase 1: contiguous loads; neg -> smem, m -> regs ----
    float pm[8];
#pragma unroll
    for (int k = 0; k < 8; k++) {
        int i = tid + k * 1024;
        sraw[i] = g_neg[i];
        pm[k]   = g_posm[i];
    }
    for (int i = tid; i < NBINS; i += 1024) shist[i] = 0;
    __syncthreads();

    // ---- phase 2: histogram (warp-aggregated atomics) ----
#pragma unroll
    for (int k = 0; k < 8; k++) {
        int b = binOf(sraw[tid + k * 1024]);
        unsigned mask = __match_any_sync(FULLM, b);
        if (lane == (__ffs(mask) - 1)) atomicAdd(&shist[b], __popc(mask));
    }
    __syncthreads();

    // ---- phase 3: exclusive scan over 4096 bins (warp-shuffle scan) ----
    const int tb = tid * 4;
    int h0 = shist[tb], h1 = shist[tb + 1], h2 = shist[tb + 2], h3 = shist[tb + 3];
    int tsum = h0 + h1 + h2 + h3;
    int v = tsum;
#pragma unroll
    for (int o = 1; o < 32; o <<= 1) {
        int t = __shfl_up_sync(FULLM, v, o);
        if (lane >= o) v += t;
    }
    if (lane == 31) iscan[wid] = v;             // warp totals
    __syncthreads();
    if (wid == 0) {
        int w = iscan[lane];
        int s = w;
#pragma unroll
        for (int o = 1; o < 32; o <<= 1) {
            int t = __shfl_up_sync(FULLM, s, o);
            if (lane >= o) s += t;
        }
        iscan[32 + lane] = s - w;               // exclusive warp offsets
    }
    __syncthreads();
    {
        int ex = v + iscan[32 + wid] - tsum;    // exclusive prefix for this thread
        sbinStart[tb] = ex;     scursor[tb]     = ex; ex += h0;
        sbinStart[tb + 1] = ex; scursor[tb + 1] = ex; ex += h1;
        sbinStart[tb + 2] = ex; scursor[tb + 2] = ex; ex += h2;
        sbinStart[tb + 3] = ex; scursor[tb + 3] = ex; ex += h3;
        if (tid == 1023) sbinStart[NBINS] = ex; // = BB
    }
    __syncthreads();

    // ---- phase 4: scatter into bin-grouped order (warp-aggregated) ----
#pragma unroll
    for (int k = 0; k < 8; k++) {
        float val = sraw[tid + k * 1024];
        int b = binOf(val);
        unsigned mask = __match_any_sync(FULLM, b);
        int leader = __ffs(mask) - 1;
        int pos0 = 0;
        if (lane == leader) pos0 = atomicAdd(&scursor[b], __popc(mask));
        pos0 = __shfl_sync(FULLM, pos0, leader);
        ssorted[pos0 + __popc(mask & ((1u << lane) - 1u))] = val;
    }
    __syncthreads();   // sraw/shist/scursor dead from here

    // ---- phase 5: element-level suffix sums (double), warp-shuffle suffix scan ----
    const int base8 = tid * 8;
    double tl1[8], tl2[8];
    double a1 = 0.0, a2 = 0.0;
#pragma unroll
    for (int k = 7; k >= 0; --k) {
        float n = ssorted[base8 + k];
        a1 += (double)n;
        a2 += (double)n * (double)n;
        tl1[k] = a1; tl2[k] = a2;
    }
    double s1 = a1, s2 = a2;
#pragma unroll
    for (int o = 1; o < 32; o <<= 1) {
        double t1 = __shfl_down_sync(FULLM, s1, o);
        double t2 = __shfl_down_sync(FULLM, s2, o);
        if (lane + o < 32) { s1 += t1; s2 += t2; }
    }
    if (lane == 0) { p1[wid] = s1; p2[wid] = s2; }  // warp totals
    __syncthreads();
    if (wid == 0) {
        double w1 = p1[lane], w2 = p2[lane];
        double e1 = w1, e2 = w2;
#pragma unroll
        for (int o = 1; o < 32; o <<= 1) {
            double t1 = __shfl_down_sync(FULLM, e1, o);
            double t2 = __shfl_down_sync(FULLM, e2, o);
            if (lane + o < 32) { e1 += t1; e2 += t2; }
        }
        p1[32 + lane] = e1 - w1;               // exclusive suffix of higher warps
        p2[32 + lane] = e2 - w2;
    }
    __syncthreads();
    {
        double o1 = s1 + p1[32 + wid] - a1;    // sum strictly after this thread's chunk
        double o2 = s2 + p2[32 + wid] - a2;
#pragma unroll
        for (int k = 0; k < 8; k++) {
            sS1[base8 + k] = tl1[k] + o1;
            sS2[base8 + k] = tl2[k] + o2;
        }
        if (tid == 0) { sS1[BB] = 0.0; sS2[BB] = 0.0; }
    }
    __syncthreads();

    // ---- phase 6: queries + warp reduction ----
    double acc = 0.0;
    int vc = 0;
#pragma unroll
    for (int k = 0; k < 8; k++) {
        float m = pm[k];
        if (!(m < 1.0f)) continue;       // invalid (+INF)
        vc++;
        long long cnt; double S1, S2;
        if (m <= 0.0f) {
            cnt = BB; S1 = sS1[0]; S2 = sS2[0];
        } else {
            int b = binOf(m); if (b > NBINS - 1) b = NBINS - 1;
            int st = sbinStart[b], en = sbinStart[b + 1];
            cnt = BB - en; S1 = sS1[en]; S2 = sS2[en];
            for (int t = st; t < en; t++) {          // exact boundary-bin scan
                float n = ssorted[t];
                if (n > m) { cnt++; S1 += (double)n; S2 += (double)n * (double)n; }
            }
        }
        double md = (double)m;
        acc += (double)cnt * md * md - 2.0 * md * S1 + S2;
    }
#pragma unroll
    for (int o = 16; o; o >>= 1) {
        acc += __shfl_down_sync(FULLM, acc, o);
        vc  += __shfl_down_sync(FULLM, vc,  o);
    }
    if (lane == 0) { p1[wid] = acc; iscan[wid] = vc; }
    __syncthreads();
    if (tid == 0) {
        double s = 0.0; int c = 0;
#pragma unroll
        for (int w = 0; w < 32; w++) { s += p1[w]; c += iscan[w]; }
        out[0] = (float)(s / ((double)c + 1.0) / ((double)BB + 1.0));
    }
}

// ---------------- launch ----------------
extern "C" void kernel_launch(void* const* d_in, const int* in_sizes, int n_in,
                              void* d_out, int out_size) {
    const float* x = (const float*)d_in[0];
    const int*   y = (const int*)d_in[1];

    k_row<<<BB, 128>>>(x, y);
    k_pos<<<32, 256>>>(x, y);
    cudaFuncSetAttribute(k_main, cudaFuncAttributeMaxDynamicSharedMemorySize, K2_SMEM);
    k_main<<<1, 1024, K2_SMEM>>>((float*)d_out);
}